// round 15
// baseline (speedup 1.0000x reference)
#include <cuda_runtime.h>
#include <cuda_fp16.h>
#include <cstdint>

#define N_NODES   100000
#define N_PAD     100096          // 782 * 128
#define NUM_RELS  16
#define NUM_BASES 8
#define D         128
#define KG        1024            // NUM_BASES*D
#define KDIM      1152            // KG + D (full GEMM K)

// ---------------- scratch (device globals; zero-initialized at load) ----------
__device__ __half g_Ah[(size_t)N_PAD * KDIM];   // [Npad, 1152] fp16 A; k<1024 order f*8+b
__device__ __half g_W3[3][128 * KDIM];          // per-layer weights, [n][k], same k order
__device__ __half g_ch[3][(size_t)N_NODES * 128]; // per-layer coeff rows ch[n][r*8+b]
__device__ __half g_hx[(size_t)N_PAD * D];      // fp16 copy of input x
__device__ __half g_h0[(size_t)N_PAD * D];      // fp16 hidden
__device__ __half g_h1[(size_t)N_PAD * D];
__device__ int   g_cnt[N_NODES];
__device__ int   g_cnt2[N_NODES * NUM_RELS];
__device__ int   g_off[N_NODES + 1];
__device__ int   g_cur[N_NODES];
__device__ int   g_csr[1600000];                // packed (type<<17)|src, grouped by dst

// ---------------- PTX helpers -------------------------------------------------
__device__ __forceinline__ uint32_t s2u(const void* p) {
    return (uint32_t)__cvta_generic_to_shared(p);
}
__device__ __forceinline__ void cp16(uint32_t smem, const void* gmem) {
    asm volatile("cp.async.cg.shared.global [%0], [%1], 16;\n" :: "r"(smem), "l"(gmem));
}
#define CP_COMMIT() asm volatile("cp.async.commit_group;\n" ::: "memory")
#define CP_WAIT(N)  asm volatile("cp.async.wait_group %0;\n" :: "n"(N) : "memory")

__device__ __forceinline__ void ldsm4(uint32_t& r0, uint32_t& r1, uint32_t& r2, uint32_t& r3,
                                      uint32_t addr) {
    asm volatile("ldmatrix.sync.aligned.m8n8.x4.shared.b16 {%0,%1,%2,%3}, [%4];"
                 : "=r"(r0), "=r"(r1), "=r"(r2), "=r"(r3) : "r"(addr));
}
__device__ __forceinline__ void ldsm4t(uint32_t& r0, uint32_t& r1, uint32_t& r2, uint32_t& r3,
                                       uint32_t addr) {
    asm volatile("ldmatrix.sync.aligned.m8n8.x4.trans.shared.b16 {%0,%1,%2,%3}, [%4];"
                 : "=r"(r0), "=r"(r1), "=r"(r2), "=r"(r3) : "r"(addr));
}
__device__ __forceinline__ void mma_f16(float4& c,
                                        uint32_t a0, uint32_t a1, uint32_t a2, uint32_t a3,
                                        uint32_t b0, uint32_t b1) {
    asm volatile(
        "mma.sync.aligned.m16n8k16.row.col.f32.f16.f16.f32 "
        "{%0,%1,%2,%3}, {%4,%5,%6,%7}, {%8,%9}, {%0,%1,%2,%3};\n"
        : "+f"(c.x), "+f"(c.y), "+f"(c.z), "+f"(c.w)
        : "r"(a0), "r"(a1), "r"(a2), "r"(a3), "r"(b0), "r"(b1));
}

// ---------------- count degrees (total + per-rel) + x -> fp16 ------------------
// g_cnt zeroed by previous call's k_scan; g_cnt2 zeroed by k_scatter_coef.
__global__ void k_count_x(const int* __restrict__ dst, const int* __restrict__ typ,
                          int E, const float* __restrict__ x) {
    int i = blockIdx.x * blockDim.x + threadIdx.x;
    if (i < E) {
        const int dn = dst[i];
        atomicAdd(&g_cnt[dn], 1);
        atomicAdd(&g_cnt2[dn * NUM_RELS + typ[i]], 1);
    }
    if (i < N_NODES * (D / 2)) {
        float2 v = reinterpret_cast<const float2*>(x)[i];
        reinterpret_cast<__half2*>(g_hx)[i] = __floats2half2_rn(v.x, v.y);
    }
}

__global__ void k_scan() {
    __shared__ int ssum[1024];
    const int chunk = (N_NODES + 1023) / 1024;
    int t = threadIdx.x;
    int b = t * chunk;
    int e = b + chunk; if (e > N_NODES) e = N_NODES;
    int s = 0;
    for (int i = b; i < e; ++i) s += g_cnt[i];
    ssum[t] = s;
    __syncthreads();
    for (int off = 1; off < 1024; off <<= 1) {
        int v = (t >= off) ? ssum[t - off] : 0;
        __syncthreads();
        ssum[t] += v;
        __syncthreads();
    }
    int run = (t == 0) ? 0 : ssum[t - 1];
    for (int i = b; i < e; ++i) {
        g_off[i] = run; g_cur[i] = run;
        run += g_cnt[i];
        g_cnt[i] = 0;                    // re-zero for next kernel_launch call
    }
    if (t == 0) g_off[N_NODES] = ssum[1023];
}

// ---------------- scatter + per-layer coefficient emit (fused) -----------------
__global__ void k_scatter_coef(const int* __restrict__ src, const int* __restrict__ dst,
                               const int* __restrict__ typ, int E,
                               const float* __restrict__ comp0,
                               const float* __restrict__ comp1,
                               const float* __restrict__ comp2) {
    int i = blockIdx.x * blockDim.x + threadIdx.x;
    if (i < E) {
        int p = atomicAdd(&g_cur[dst[i]], 1);
        g_csr[p] = (typ[i] << 17) | src[i];
    }
    if (i < N_NODES * NUM_RELS) {
        const int r = i & 15;
        const size_t n = (size_t)(i >> 4);
        int c = g_cnt2[i];
        g_cnt2[i] = 0;                   // re-zero for next kernel_launch call
        const float inv = (c > 0) ? (1.0f / (float)c) : 0.0f;
        const size_t o = n * 128 + r * 8;
        #pragma unroll
        for (int l = 0; l < 3; ++l) {
            const float* comp = (l == 0) ? comp0 : (l == 1) ? comp1 : comp2;
            const float4 a = *reinterpret_cast<const float4*>(comp + r * 8);
            const float4 b = *reinterpret_cast<const float4*>(comp + r * 8 + 4);
            __half2 h0 = __floats2half2_rn(a.x * inv, a.y * inv);
            __half2 h1 = __floats2half2_rn(a.z * inv, a.w * inv);
            __half2 h2 = __floats2half2_rn(b.x * inv, b.y * inv);
            __half2 h3 = __floats2half2_rn(b.z * inv, b.w * inv);
            uint4 u;
            u.x = *reinterpret_cast<uint32_t*>(&h0);
            u.y = *reinterpret_cast<uint32_t*>(&h1);
            u.z = *reinterpret_cast<uint32_t*>(&h2);
            u.w = *reinterpret_cast<uint32_t*>(&h3);
            *reinterpret_cast<uint4*>(&g_ch[l][o]) = u;
        }
    }
}

// ---------------- weights: all 3 layers, k<KG reordered as k = f*8 + b ---------
__global__ void k_make_w_all(const float* __restrict__ bases0, const float* __restrict__ root0,
                             const float* __restrict__ bases1, const float* __restrict__ root1,
                             const float* __restrict__ bases2, const float* __restrict__ root2) {
    int idx = blockIdx.x * blockDim.x + threadIdx.x;
    if (idx >= 3 * 128 * KDIM) return;
    const int layer = idx / (128 * KDIM);
    const int rem = idx % (128 * KDIM);
    const int n = rem / KDIM, k = rem % KDIM;
    const float* bases = (layer == 0) ? bases0 : (layer == 1) ? bases1 : bases2;
    const float* root  = (layer == 0) ? root0  : (layer == 1) ? root1  : root2;
    const int dout     = (layer == 2) ? 40 : 128;
    float v = 0.f;
    if (n < dout) {
        if (k < KG) {
            const int f = k >> 3, b = k & 7;          // k = f*8 + b
            v = bases[(b * 128 + f) * dout + n];
        } else {
            v = root[(k - KG) * dout + n];
        }
    }
    g_W3[layer][rem] = __float2half_rn(v);
}

// ---------------- pull-aggregate: tensor-core basis combine -------------------
// Per warp, per node: D[f][b] += X^T[f][e] * C[e][b] via mma.m16n8k16.
// Coefficients precomputed per (layer, node) in g_ch -> one LDG.128 row load.
// Per-warp smem (WB=9216): [0,8704) 2x(16x272B) tile; [8704,8976) chp[17][8];
//                          [8976,9104) rel ids r[2][16]
#define PULL_WARPS 8
#define WB 9216
#define TILE_PITCH 272
#define BUF_B 4352

__global__ void k_pull(const __half* __restrict__ hin, const __half* __restrict__ ch) {
    extern __shared__ char dsm[];
    const int w = threadIdx.x >> 5, lane = threadIdx.x & 31;
    char* wbase = dsm + w * WB;
    char* tilep = wbase;
    __half* chp = (__half*)(wbase + 8704);
    int* rp     = (int*)(wbase + 8976);
    const uint32_t tile_u = s2u(tilep);

    // chp row 16 (padding relation) = 0, written once
    if (lane < 4) reinterpret_cast<uint32_t*>(chp + 128)[lane] = 0u;
    __syncwarp();

    const int wg = blockIdx.x * PULL_WARPS + w;
    const int nwarps = gridDim.x * PULL_WARPS;
    const int halfsel = lane >> 4;        // 0/1: which of the 2 rows per pass
    const int c16 = lane & 15;            // 16B chunk within 256B row

    for (int n = wg; n < N_NODES; n += nwarps) {
        const int off = g_off[n], end = g_off[n + 1];

        // stage this node's coefficient row (rows 0..15)
        if (lane < 16) {
            const uint4 cv = *reinterpret_cast<const uint4*>(ch + (size_t)n * 128 + lane * 8);
            *reinterpret_cast<uint4*>(chp + lane * 8) = cv;
        }

        float4 d[8];
        #pragma unroll
        for (int j = 0; j < 8; ++j) d[j] = make_float4(0.f, 0.f, 0.f, 0.f);

        const int nc = (end - off + 15) >> 4;
        uint4 st[8];
        int rmy;

        auto ldg = [&](int chunk) {
            const int base_e = off + (chunk << 4);
            const int rem = end - base_e;
            int src = 0;
            rmy = 16;
            if (lane < 16 && lane < rem) {
                const int p = g_csr[base_e + lane];
                src = p & 131071;
                rmy = p >> 17;
            }
            #pragma unroll
            for (int pass = 0; pass < 8; ++pass) {
                const int row = pass * 2 + halfsel;
                const int rsrc = __shfl_sync(0xffffffffu, src, row);
                if (row < rem)
                    st[pass] = *reinterpret_cast<const uint4*>(
                        hin + (size_t)rsrc * D + c16 * 8);
                else
                    st[pass] = make_uint4(0u, 0u, 0u, 0u);
            }
        };
        auto sts = [&](int buf) {
            if (lane < 16) rp[buf * 16 + lane] = rmy;
            #pragma unroll
            for (int pass = 0; pass < 8; ++pass) {
                const int row = pass * 2 + halfsel;
                *reinterpret_cast<uint4*>(tilep + buf * BUF_B + row * TILE_PITCH + c16 * 16)
                    = st[pass];
            }
        };
        auto consume = [&](int buf) {
            const int k0 = (lane & 3) * 2;
            const int nn = lane >> 2;               // basis 0..7
            const int* rb = rp + buf * 16;
            const __half h0 = chp[rb[k0] * 8 + nn];
            const __half h1 = chp[rb[k0 + 1] * 8 + nn];
            const __half h2 = chp[rb[k0 + 8] * 8 + nn];
            const __half h3 = chp[rb[k0 + 9] * 8 + nn];
            __half2 B0 = __halves2half2(h0, h1), B1 = __halves2half2(h2, h3);
            const uint32_t b0 = *reinterpret_cast<uint32_t*>(&B0);
            const uint32_t b1 = *reinterpret_cast<uint32_t*>(&B1);
            const uint32_t ab = tile_u + buf * BUF_B
                + ((lane & 7) + ((lane >> 4) << 3)) * TILE_PITCH
                + ((lane >> 3) & 1) * 16;
            #pragma unroll
            for (int j = 0; j < 8; ++j) {
                uint32_t a0, a1, a2, a3;
                ldsm4t(a0, a1, a2, a3, ab + j * 32);
                mma_f16(d[j], a0, a1, a2, a3, b0, b1);
            }
        };

        if (nc > 0) {
            ldg(0);
            sts(0);
            __syncwarp();
            for (int i = 0; i < nc; ++i) {
                const bool more = (i + 1 < nc);
                if (more) ldg(i + 1);          // LDGs fly while we consume
                consume(i & 1);
                if (more) { sts((i + 1) & 1); __syncwarp(); }
            }
        }

        // epilogue: D fragment (f, b) -> A[k = f*8 + b], coalesced half2 stores
        __half* Ar = g_Ah + (size_t)n * KDIM;
        #pragma unroll
        for (int j = 0; j < 8; ++j) {
            const int f = 16 * j + (lane >> 2);
            const int b = 2 * (lane & 3);
            __half2 xy = __floats2half2_rn(d[j].x, d[j].y);
            __half2 zw = __floats2half2_rn(d[j].z, d[j].w);
            *reinterpret_cast<__half2*>(Ar + f * 8 + b) = xy;
            *reinterpret_cast<__half2*>(Ar + (f + 8) * 8 + b) = zw;
        }
        const uint2 sv = *reinterpret_cast<const uint2*>(hin + (size_t)n * D + lane * 4);
        *reinterpret_cast<uint2*>(Ar + KG + lane * 4) = sv;
        __syncwarp();
    }
}

// ---------------- fp16 tensor-core GEMM (ldmatrix + 3-stage cp.async) ---------
template <int BN, int HALF_OUT>
__global__ __launch_bounds__(256, 2) void k_gemm(const __half* __restrict__ W,
                                                 const float* __restrict__ bias,
                                                 void* __restrict__ outp,
                                                 int Nout, int relu, int predM) {
    constexpr int BK   = 32;
    constexpr int ROWB = (BK + 8) * 2;              // 80 bytes per smem row
    constexpr int JT   = BN / 32;                   // n8 tiles per warp
    constexpr int STAGE = (128 + BN) * ROWB;        // bytes per pipeline stage
    constexpr int NK   = KDIM / BK;                 // 36
    extern __shared__ char sm[];

    const int tid = threadIdx.x, wid = tid >> 5, lane = tid & 31;
    const int wm = wid >> 2, wn = wid & 3;
    const int g = lane >> 2, t = lane & 3;
    const int m0 = blockIdx.x * 128;
    const uint32_t smb = s2u(sm);

    const uint32_t a_base = (uint32_t)((wm * 64 + (lane & 15)) * ROWB + (lane >> 4) * 16);
    const uint32_t b_base = (uint32_t)((wn * (JT * 8) + ((lane >> 4) & 1) * 8 + (lane & 7)) * ROWB
                                       + ((lane >> 3) & 1) * 16);

    float4 c[4][JT];
    #pragma unroll
    for (int i = 0; i < 4; ++i)
        #pragma unroll
        for (int j = 0; j < JT; ++j) c[i][j] = make_float4(0.f, 0.f, 0.f, 0.f);

    auto load_stage = [&](int st, int kt) {
        const uint32_t base = smb + st * STAGE;
        #pragma unroll
        for (int i = 0; i < 2; ++i) {
            const int task = tid + i * 256;
            const int row = task >> 2, ch = task & 3;
            cp16(base + row * ROWB + ch * 16,
                 g_Ah + (size_t)(m0 + row) * KDIM + kt + ch * 8);
        }
        #pragma unroll
        for (int i = 0; i < (BN * 4) / 256; ++i) {
            const int task = tid + i * 256;
            const int row = task >> 2, ch = task & 3;
            cp16(base + 128 * ROWB + row * ROWB + ch * 16,
                 W + (size_t)row * KDIM + kt + ch * 8);
        }
        CP_COMMIT();
    };

    load_stage(0, 0);
    load_stage(1, BK);

    for (int it = 0; it < NK; ++it) {
        if (it < NK - 1) { CP_WAIT(1); } else { CP_WAIT(0); }
        __syncthreads();
        if (it + 2 < NK) load_stage((it + 2) % 3, (it + 2) * BK);

        const uint32_t sA = smb + (it % 3) * STAGE;
        const uint32_t sB = sA + 128 * ROWB;
        #pragma unroll
        for (int kk = 0; kk < BK; kk += 16) {
            uint32_t a[4][4];
            #pragma unroll
            for (int i = 0; i < 4; ++i)
                ldsm4(a[i][0], a[i][1], a[i][2], a[i][3],
                      sA + a_base + i * (16 * ROWB) + kk * 2);
            uint32_t b[JT][2];
            #pragma unroll
            for (int jc = 0; jc < JT / 2; ++jc)
                ldsm4(b[2 * jc][0], b[2 * jc][1], b[2 * jc + 1][0], b[2 * jc + 1][1],
                      sB + b_base + jc * (16 * ROWB) + kk * 2);
            #pragma unroll
            for (int i = 0; i < 4; ++i)
                #pragma unroll
                for (int j = 0; j < JT; ++j)
                    mma_f16(c[i][j], a[i][0], a[i][1], a[i][2], a[i][3], b[j][0], b[j][1]);
        }
    }

    // epilogue
    #pragma unroll
    for (int i = 0; i < 4; ++i) {
        const int r0 = m0 + wm * 64 + i * 16 + g;
        #pragma unroll
        for (int j = 0; j < JT; ++j) {
            const int col = wn * (JT * 8) + j * 8 + 2 * t;
            if (col < Nout) {
                float b0 = bias[col];
                float b1 = (col + 1 < Nout) ? bias[col + 1] : 0.f;
                float v00 = c[i][j].x + b0, v01 = c[i][j].y + b1;
                float v10 = c[i][j].z + b0, v11 = c[i][j].w + b1;
                if (relu) {
                    v00 = fmaxf(v00, 0.f); v01 = fmaxf(v01, 0.f);
                    v10 = fmaxf(v10, 0.f); v11 = fmaxf(v11, 0.f);
                }
                if (HALF_OUT) {
                    __half* o = (__half*)outp;
                    __half2 h0 = __floats2half2_rn(v00, v01);
                    __half2 h1 = __floats2half2_rn(v10, v11);
                    *reinterpret_cast<__half2*>(o + (size_t)r0 * Nout + col) = h0;
                    *reinterpret_cast<__half2*>(o + (size_t)(r0 + 8) * Nout + col) = h1;
                } else {
                    float* o = (float*)outp;
                    const bool c1ok = (col + 1 < Nout);
                    if (!predM || r0 < N_NODES) {
                        o[(size_t)r0 * Nout + col] = v00;
                        if (c1ok) o[(size_t)r0 * Nout + col + 1] = v01;
                    }
                    if (!predM || r0 + 8 < N_NODES) {
                        o[(size_t)(r0 + 8) * Nout + col] = v10;
                        if (c1ok) o[(size_t)(r0 + 8) * Nout + col + 1] = v11;
                    }
                }
            }
        }
    }
}

// ---------------- launch ------------------------------------------------------
extern "C" void kernel_launch(void* const* d_in, const int* in_sizes, int n_in,
                              void* d_out, int out_size) {
    const float* x      = (const float*)d_in[0];
    const int*   esrc   = (const int*)  d_in[1];
    const int*   edst   = (const int*)  d_in[2];
    const int*   etyp   = (const int*)  d_in[3];
    const float* bases0 = (const float*)d_in[4];
    const float* comp0  = (const float*)d_in[5];
    const float* root0  = (const float*)d_in[6];
    const float* bias0  = (const float*)d_in[7];
    const float* bases1 = (const float*)d_in[8];
    const float* comp1  = (const float*)d_in[9];
    const float* root1  = (const float*)d_in[10];
    const float* bias1  = (const float*)d_in[11];
    const float* bases2 = (const float*)d_in[12];
    const float* comp2  = (const float*)d_in[13];
    const float* root2  = (const float*)d_in[14];
    const float* bias2  = (const float*)d_in[15];
    float* out = (float*)d_out;
    const int E = in_sizes[1];

    void* p;
    cudaGetSymbolAddress(&p, g_hx); __half* hx = (__half*)p;
    cudaGetSymbolAddress(&p, g_h0); __half* h0 = (__half*)p;
    cudaGetSymbolAddress(&p, g_h1); __half* h1 = (__half*)p;
    cudaGetSymbolAddress(&p, g_W3); __half* w3 = (__half*)p;
    cudaGetSymbolAddress(&p, g_ch); __half* chb = (__half*)p;
    __half* w0 = w3;
    __half* w1 = w3 + (size_t)128 * KDIM;
    __half* w2 = w3 + (size_t)2 * 128 * KDIM;
    __half* ch0 = chb;
    __half* ch1 = chb + (size_t)N_NODES * 128;
    __half* ch2 = chb + (size_t)2 * N_NODES * 128;

    const int smem128 = 3 * (128 + 128) * 80;   // 61440
    const int smem64  = 3 * (128 + 64) * 80;    // 46080
    const int smemPull = PULL_WARPS * WB;       // 73728
    cudaFuncSetAttribute(k_gemm<128, 1>, cudaFuncAttributeMaxDynamicSharedMemorySize, smem128);
    cudaFuncSetAttribute(k_gemm<64, 0>,  cudaFuncAttributeMaxDynamicSharedMemorySize, smem64);
    cudaFuncSetAttribute(k_pull, cudaFuncAttributeMaxDynamicSharedMemorySize, smemPull);

    const int pgrid = 304;            // 2 CTAs/SM * 152 SMs — persistent
    const int ggrid = N_PAD / 128;    // 782

    // front-end: counts (+x2h), scan (re-zeros g_cnt), scatter + coeff emit
    k_count_x<<<(N_NODES * (D / 2) + 255) / 256, 256>>>(edst, etyp, E, x);
    k_scan<<<1, 1024>>>();
    k_scatter_coef<<<(E + 255) / 256, 256>>>(esrc, edst, etyp, E, comp0, comp1, comp2);

    // layer 0 (pull in ncu capture slot 4)
    k_pull<<<pgrid, 256, smemPull>>>(hx, ch0);
    k_make_w_all<<<(3 * 128 * KDIM + 255) / 256, 256>>>(bases0, root0, bases1, root1,
                                                        bases2, root2);
    k_gemm<128, 1><<<ggrid, 256, smem128>>>(w0, bias0, h0, D, 1, 0);

    // layer 1
    k_pull<<<pgrid, 256, smemPull>>>(h0, ch1);
    k_gemm<128, 1><<<ggrid, 256, smem128>>>(w1, bias1, h1, D, 1, 0);

    // layer 2 (d_out = 40)
    k_pull<<<pgrid, 256, smemPull>>>(h1, ch2);
    k_gemm<64, 0><<<ggrid, 256, smem64>>>(w2, bias2, out, 40, 0, 1);
}

// round 16
// speedup vs baseline: 1.1057x; 1.1057x over previous
#include <cuda_runtime.h>
#include <cuda_fp16.h>
#include <cstdint>

#define N_NODES   100000
#define N_PAD     100096          // 782 * 128
#define NUM_RELS  16
#define NUM_BASES 8
#define D         128
#define KG        1024            // NUM_BASES*D (A width; self block read from hin)
#define KDIM      1152            // KG + D (full GEMM K)

// ---------------- scratch (device globals; zero-initialized at load) ----------
__device__ __half g_Ah[(size_t)N_PAD * KG];     // [Npad, 1024] fp16 A; k order f*8+b
__device__ __half g_W3[3][128 * KDIM];          // per-layer weights, [n][k]
__device__ float  g_invf[N_NODES * NUM_RELS];   // 1/deg(n,r), 0 if deg==0
__device__ __half g_hx[(size_t)N_PAD * D];      // fp16 copy of input x
__device__ __half g_h0[(size_t)N_PAD * D];      // fp16 hidden
__device__ __half g_h1[(size_t)N_PAD * D];
__device__ int   g_cnt[N_NODES];
__device__ int   g_cnt2[N_NODES * NUM_RELS];
__device__ int   g_off[N_NODES + 1];
__device__ int   g_cur[N_NODES];
__device__ int   g_csr[1600000];                // packed (type<<17)|src, grouped by dst

// ---------------- PTX helpers -------------------------------------------------
__device__ __forceinline__ uint32_t s2u(const void* p) {
    return (uint32_t)__cvta_generic_to_shared(p);
}
__device__ __forceinline__ void cp16(uint32_t smem, const void* gmem) {
    asm volatile("cp.async.cg.shared.global [%0], [%1], 16;\n" :: "r"(smem), "l"(gmem));
}
#define CP_COMMIT() asm volatile("cp.async.commit_group;\n" ::: "memory")
#define CP_WAIT(N)  asm volatile("cp.async.wait_group %0;\n" :: "n"(N) : "memory")

__device__ __forceinline__ void ldsm4(uint32_t& r0, uint32_t& r1, uint32_t& r2, uint32_t& r3,
                                      uint32_t addr) {
    asm volatile("ldmatrix.sync.aligned.m8n8.x4.shared.b16 {%0,%1,%2,%3}, [%4];"
                 : "=r"(r0), "=r"(r1), "=r"(r2), "=r"(r3) : "r"(addr));
}
__device__ __forceinline__ void ldsm4t(uint32_t& r0, uint32_t& r1, uint32_t& r2, uint32_t& r3,
                                       uint32_t addr) {
    asm volatile("ldmatrix.sync.aligned.m8n8.x4.trans.shared.b16 {%0,%1,%2,%3}, [%4];"
                 : "=r"(r0), "=r"(r1), "=r"(r2), "=r"(r3) : "r"(addr));
}
__device__ __forceinline__ void mma_f16(float4& c,
                                        uint32_t a0, uint32_t a1, uint32_t a2, uint32_t a3,
                                        uint32_t b0, uint32_t b1) {
    asm volatile(
        "mma.sync.aligned.m16n8k16.row.col.f32.f16.f16.f32 "
        "{%0,%1,%2,%3}, {%4,%5,%6,%7}, {%8,%9}, {%0,%1,%2,%3};\n"
        : "+f"(c.x), "+f"(c.y), "+f"(c.z), "+f"(c.w)
        : "r"(a0), "r"(a1), "r"(a2), "r"(a3), "r"(b0), "r"(b1));
}

// ---------------- count degrees (total + per-rel) + x -> fp16 ------------------
// g_cnt zeroed by previous call's k_scan; g_cnt2 zeroed by k_scatter_coef.
__global__ void k_count_x(const int* __restrict__ dst, const int* __restrict__ typ,
                          int E, const float* __restrict__ x) {
    int i = blockIdx.x * blockDim.x + threadIdx.x;
    if (i < E) {
        const int dn = dst[i];
        atomicAdd(&g_cnt[dn], 1);
        atomicAdd(&g_cnt2[dn * NUM_RELS + typ[i]], 1);
    }
    if (i < N_NODES * (D / 2)) {
        float2 v = reinterpret_cast<const float2*>(x)[i];
        reinterpret_cast<__half2*>(g_hx)[i] = __floats2half2_rn(v.x, v.y);
    }
}

__global__ void k_scan() {
    __shared__ int ssum[1024];
    const int chunk = (N_NODES + 1023) / 1024;
    int t = threadIdx.x;
    int b = t * chunk;
    int e = b + chunk; if (e > N_NODES) e = N_NODES;
    int s = 0;
    for (int i = b; i < e; ++i) s += g_cnt[i];
    ssum[t] = s;
    __syncthreads();
    for (int off = 1; off < 1024; off <<= 1) {
        int v = (t >= off) ? ssum[t - off] : 0;
        __syncthreads();
        ssum[t] += v;
        __syncthreads();
    }
    int run = (t == 0) ? 0 : ssum[t - 1];
    for (int i = b; i < e; ++i) {
        g_off[i] = run; g_cur[i] = run;
        run += g_cnt[i];
        g_cnt[i] = 0;                    // re-zero for next kernel_launch call
    }
    if (t == 0) g_off[N_NODES] = ssum[1023];
}

// ---------------- scatter + inverse-degree emit (fused) ------------------------
__global__ void k_scatter_coef(const int* __restrict__ src, const int* __restrict__ dst,
                               const int* __restrict__ typ, int E) {
    int i = blockIdx.x * blockDim.x + threadIdx.x;
    if (i < E) {
        int p = atomicAdd(&g_cur[dst[i]], 1);
        g_csr[p] = (typ[i] << 17) | src[i];
    }
    if (i < N_NODES * NUM_RELS) {
        int c = g_cnt2[i];
        g_cnt2[i] = 0;                   // re-zero for next kernel_launch call
        g_invf[i] = (c > 0) ? (1.0f / (float)c) : 0.0f;
    }
}

// ---------------- weights: all 3 layers, k<KG reordered as k = f*8 + b ---------
__global__ void k_make_w_all(const float* __restrict__ bases0, const float* __restrict__ root0,
                             const float* __restrict__ bases1, const float* __restrict__ root1,
                             const float* __restrict__ bases2, const float* __restrict__ root2) {
    int idx = blockIdx.x * blockDim.x + threadIdx.x;
    if (idx >= 3 * 128 * KDIM) return;
    const int layer = idx / (128 * KDIM);
    const int rem = idx % (128 * KDIM);
    const int n = rem / KDIM, k = rem % KDIM;
    const float* bases = (layer == 0) ? bases0 : (layer == 1) ? bases1 : bases2;
    const float* root  = (layer == 0) ? root0  : (layer == 1) ? root1  : root2;
    const int dout     = (layer == 2) ? 40 : 128;
    float v = 0.f;
    if (n < dout) {
        if (k < KG) {
            const int f = k >> 3, b = k & 7;          // k = f*8 + b
            v = bases[(b * 128 + f) * dout + n];
        } else {
            v = root[(k - KG) * dout + n];
        }
    }
    g_W3[layer][rem] = __float2half_rn(v);
}

// ---------------- pull-aggregate: tensor-core basis combine -------------------
// Per warp, per node: D[f][b] += X^T[f][e] * C[e][b] via mma.m16n8k16.
// comp staged fp32 in per-warp smem once; per node one inv-row load rebuilds chp.
// Per-warp smem (WB=9728): [0,8704) 2x(16x272B) tile; [8704,8976) chp[17][8];
//   [8976,9104) rel ids r[2][16]; [9104,9616) comp_f[128]
#define PULL_WARPS 8
#define WB 9728
#define TILE_PITCH 272
#define BUF_B 4352

__global__ void k_pull(const __half* __restrict__ hin, const float* __restrict__ comp,
                       const float* __restrict__ invf) {
    extern __shared__ char dsm[];
    const int w = threadIdx.x >> 5, lane = threadIdx.x & 31;
    char* wbase = dsm + w * WB;
    char* tilep = wbase;
    __half* chp = (__half*)(wbase + 8704);
    int* rp     = (int*)(wbase + 8976);
    float* cfp  = (float*)(wbase + 9104);
    const uint32_t tile_u = s2u(tilep);

    // once: stage comp (fp32) and zero chp padding row 16
    *reinterpret_cast<float4*>(cfp + lane * 4) =
        *reinterpret_cast<const float4*>(comp + lane * 4);
    if (lane < 4) reinterpret_cast<uint32_t*>(chp + 128)[lane] = 0u;
    __syncwarp();

    const int wg = blockIdx.x * PULL_WARPS + w;
    const int nwarps = gridDim.x * PULL_WARPS;
    const int halfsel = lane >> 4;        // 0/1: which of the 2 rows per pass
    const int c16 = lane & 15;            // 16B chunk within 256B row

    for (int n = wg; n < N_NODES; n += nwarps) {
        const int off = g_off[n], end = g_off[n + 1];

        // rebuild chp: 16 lanes load inv; all lanes compute 4 entries via shfl
        float inv = 0.f;
        if (lane < 16) inv = invf[n * NUM_RELS + lane];
        #pragma unroll
        for (int q = 0; q < 4; ++q) {
            const int idx = lane + q * 32;
            const float iv = __shfl_sync(0xffffffffu, inv, idx >> 3);
            chp[idx] = __float2half_rn(cfp[idx] * iv);
        }

        float4 d[8];
        #pragma unroll
        for (int j = 0; j < 8; ++j) d[j] = make_float4(0.f, 0.f, 0.f, 0.f);

        const int nc = (end - off + 15) >> 4;
        uint4 st[8];
        int rmy;

        auto ldg = [&](int chunk) {
            const int base_e = off + (chunk << 4);
            const int rem = end - base_e;
            int src = 0;
            rmy = 16;
            if (lane < 16 && lane < rem) {
                const int p = g_csr[base_e + lane];
                src = p & 131071;
                rmy = p >> 17;
            }
            #pragma unroll
            for (int pass = 0; pass < 8; ++pass) {
                const int row = pass * 2 + halfsel;
                const int rsrc = __shfl_sync(0xffffffffu, src, row);
                if (row < rem)
                    st[pass] = *reinterpret_cast<const uint4*>(
                        hin + (size_t)rsrc * D + c16 * 8);
                else
                    st[pass] = make_uint4(0u, 0u, 0u, 0u);
            }
        };
        auto sts = [&](int buf) {
            if (lane < 16) rp[buf * 16 + lane] = rmy;
            #pragma unroll
            for (int pass = 0; pass < 8; ++pass) {
                const int row = pass * 2 + halfsel;
                *reinterpret_cast<uint4*>(tilep + buf * BUF_B + row * TILE_PITCH + c16 * 16)
                    = st[pass];
            }
        };
        auto consume = [&](int buf) {
            const int k0 = (lane & 3) * 2;
            const int nn = lane >> 2;               // basis 0..7
            const int* rb = rp + buf * 16;
            const __half h0 = chp[rb[k0] * 8 + nn];
            const __half h1 = chp[rb[k0 + 1] * 8 + nn];
            const __half h2 = chp[rb[k0 + 8] * 8 + nn];
            const __half h3 = chp[rb[k0 + 9] * 8 + nn];
            __half2 B0 = __halves2half2(h0, h1), B1 = __halves2half2(h2, h3);
            const uint32_t b0 = *reinterpret_cast<uint32_t*>(&B0);
            const uint32_t b1 = *reinterpret_cast<uint32_t*>(&B1);
            const uint32_t ab = tile_u + buf * BUF_B
                + ((lane & 7) + ((lane >> 4) << 3)) * TILE_PITCH
                + ((lane >> 3) & 1) * 16;
            #pragma unroll
            for (int j = 0; j < 8; ++j) {
                uint32_t a0, a1, a2, a3;
                ldsm4t(a0, a1, a2, a3, ab + j * 32);
                mma_f16(d[j], a0, a1, a2, a3, b0, b1);
            }
        };

        if (nc > 0) {
            ldg(0);
            sts(0);
            __syncwarp();
            for (int i = 0; i < nc; ++i) {
                const bool more = (i + 1 < nc);
                if (more) ldg(i + 1);          // LDGs fly while we consume
                consume(i & 1);
                if (more) { sts((i + 1) & 1); __syncwarp(); }
            }
        }

        // epilogue: D fragment (f, b) -> A[k = f*8 + b], coalesced half2 stores
        __half* Ar = g_Ah + (size_t)n * KG;
        #pragma unroll
        for (int j = 0; j < 8; ++j) {
            const int f = 16 * j + (lane >> 2);
            const int b = 2 * (lane & 3);
            __half2 xy = __floats2half2_rn(d[j].x, d[j].y);
            __half2 zw = __floats2half2_rn(d[j].z, d[j].w);
            *reinterpret_cast<__half2*>(Ar + f * 8 + b) = xy;
            *reinterpret_cast<__half2*>(Ar + (f + 8) * 8 + b) = zw;
        }
        __syncwarp();
    }
}

// ---------------- fp16 tensor-core GEMM (ldmatrix + 3-stage cp.async) ---------
// A = [g_Ah (k<1024, pitch KG) | hin (k>=1024, pitch D)]; B = W[128][1152]
template <int BN, int HALF_OUT>
__global__ __launch_bounds__(256, 2) void k_gemm(const __half* __restrict__ W,
                                                 const __half* __restrict__ hin,
                                                 const float* __restrict__ bias,
                                                 void* __restrict__ outp,
                                                 int Nout, int relu, int predM) {
    constexpr int BK   = 32;
    constexpr int ROWB = (BK + 8) * 2;              // 80 bytes per smem row
    constexpr int JT   = BN / 32;                   // n8 tiles per warp
    constexpr int STAGE = (128 + BN) * ROWB;        // bytes per pipeline stage
    constexpr int NK   = KDIM / BK;                 // 36
    extern __shared__ char sm[];

    const int tid = threadIdx.x, wid = tid >> 5, lane = tid & 31;
    const int wm = wid >> 2, wn = wid & 3;
    const int g = lane >> 2, t = lane & 3;
    const int m0 = blockIdx.x * 128;
    const uint32_t smb = s2u(sm);

    const uint32_t a_base = (uint32_t)((wm * 64 + (lane & 15)) * ROWB + (lane >> 4) * 16);
    const uint32_t b_base = (uint32_t)((wn * (JT * 8) + ((lane >> 4) & 1) * 8 + (lane & 7)) * ROWB
                                       + ((lane >> 3) & 1) * 16);

    float4 c[4][JT];
    #pragma unroll
    for (int i = 0; i < 4; ++i)
        #pragma unroll
        for (int j = 0; j < JT; ++j) c[i][j] = make_float4(0.f, 0.f, 0.f, 0.f);

    auto load_stage = [&](int st, int kt) {
        const uint32_t base = smb + st * STAGE;
        #pragma unroll
        for (int i = 0; i < 2; ++i) {
            const int task = tid + i * 256;
            const int row = task >> 2, ch = task & 3;
            const __half* src = (kt < KG)
                ? g_Ah + (size_t)(m0 + row) * KG + kt + ch * 8
                : hin  + (size_t)(m0 + row) * D + (kt - KG) + ch * 8;
            cp16(base + row * ROWB + ch * 16, src);
        }
        #pragma unroll
        for (int i = 0; i < (BN * 4) / 256; ++i) {
            const int task = tid + i * 256;
            const int row = task >> 2, ch = task & 3;
            cp16(base + 128 * ROWB + row * ROWB + ch * 16,
                 W + (size_t)row * KDIM + kt + ch * 8);
        }
        CP_COMMIT();
    };

    load_stage(0, 0);
    load_stage(1, BK);

    for (int it = 0; it < NK; ++it) {
        if (it < NK - 1) { CP_WAIT(1); } else { CP_WAIT(0); }
        __syncthreads();
        if (it + 2 < NK) load_stage((it + 2) % 3, (it + 2) * BK);

        const uint32_t sA = smb + (it % 3) * STAGE;
        const uint32_t sB = sA + 128 * ROWB;
        #pragma unroll
        for (int kk = 0; kk < BK; kk += 16) {
            uint32_t a[4][4];
            #pragma unroll
            for (int i = 0; i < 4; ++i)
                ldsm4(a[i][0], a[i][1], a[i][2], a[i][3],
                      sA + a_base + i * (16 * ROWB) + kk * 2);
            uint32_t b[JT][2];
            #pragma unroll
            for (int jc = 0; jc < JT / 2; ++jc)
                ldsm4(b[2 * jc][0], b[2 * jc][1], b[2 * jc + 1][0], b[2 * jc + 1][1],
                      sB + b_base + jc * (16 * ROWB) + kk * 2);
            #pragma unroll
            for (int i = 0; i < 4; ++i)
                #pragma unroll
                for (int j = 0; j < JT; ++j)
                    mma_f16(c[i][j], a[i][0], a[i][1], a[i][2], a[i][3], b[j][0], b[j][1]);
        }
    }

    // epilogue
    #pragma unroll
    for (int i = 0; i < 4; ++i) {
        const int r0 = m0 + wm * 64 + i * 16 + g;
        #pragma unroll
        for (int j = 0; j < JT; ++j) {
            const int col = wn * (JT * 8) + j * 8 + 2 * t;
            if (col < Nout) {
                float b0 = bias[col];
                float b1 = (col + 1 < Nout) ? bias[col + 1] : 0.f;
                float v00 = c[i][j].x + b0, v01 = c[i][j].y + b1;
                float v10 = c[i][j].z + b0, v11 = c[i][j].w + b1;
                if (relu) {
                    v00 = fmaxf(v00, 0.f); v01 = fmaxf(v01, 0.f);
                    v10 = fmaxf(v10, 0.f); v11 = fmaxf(v11, 0.f);
                }
                if (HALF_OUT) {
                    __half* o = (__half*)outp;
                    __half2 h0 = __floats2half2_rn(v00, v01);
                    __half2 h1 = __floats2half2_rn(v10, v11);
                    *reinterpret_cast<__half2*>(o + (size_t)r0 * Nout + col) = h0;
                    *reinterpret_cast<__half2*>(o + (size_t)(r0 + 8) * Nout + col) = h1;
                } else {
                    float* o = (float*)outp;
                    const bool c1ok = (col + 1 < Nout);
                    if (!predM || r0 < N_NODES) {
                        o[(size_t)r0 * Nout + col] = v00;
                        if (c1ok) o[(size_t)r0 * Nout + col + 1] = v01;
                    }
                    if (!predM || r0 + 8 < N_NODES) {
                        o[(size_t)(r0 + 8) * Nout + col] = v10;
                        if (c1ok) o[(size_t)(r0 + 8) * Nout + col + 1] = v11;
                    }
                }
            }
        }
    }
}

// ---------------- launch ------------------------------------------------------
extern "C" void kernel_launch(void* const* d_in, const int* in_sizes, int n_in,
                              void* d_out, int out_size) {
    const float* x      = (const float*)d_in[0];
    const int*   esrc   = (const int*)  d_in[1];
    const int*   edst   = (const int*)  d_in[2];
    const int*   etyp   = (const int*)  d_in[3];
    const float* bases0 = (const float*)d_in[4];
    const float* comp0  = (const float*)d_in[5];
    const float* root0  = (const float*)d_in[6];
    const float* bias0  = (const float*)d_in[7];
    const float* bases1 = (const float*)d_in[8];
    const float* comp1  = (const float*)d_in[9];
    const float* root1  = (const float*)d_in[10];
    const float* bias1  = (const float*)d_in[11];
    const float* bases2 = (const float*)d_in[12];
    const float* comp2  = (const float*)d_in[13];
    const float* root2  = (const float*)d_in[14];
    const float* bias2  = (const float*)d_in[15];
    float* out = (float*)d_out;
    const int E = in_sizes[1];

    void* p;
    cudaGetSymbolAddress(&p, g_hx); __half* hx = (__half*)p;
    cudaGetSymbolAddress(&p, g_h0); __half* h0 = (__half*)p;
    cudaGetSymbolAddress(&p, g_h1); __half* h1 = (__half*)p;
    cudaGetSymbolAddress(&p, g_W3); __half* w3 = (__half*)p;
    cudaGetSymbolAddress(&p, g_invf); float* invf = (float*)p;
    __half* w0 = w3;
    __half* w1 = w3 + (size_t)128 * KDIM;
    __half* w2 = w3 + (size_t)2 * 128 * KDIM;

    const int smem128 = 3 * (128 + 128) * 80;   // 61440
    const int smem64  = 3 * (128 + 64) * 80;    // 46080
    const int smemPull = PULL_WARPS * WB;       // 77824
    cudaFuncSetAttribute(k_gemm<128, 1>, cudaFuncAttributeMaxDynamicSharedMemorySize, smem128);
    cudaFuncSetAttribute(k_gemm<64, 0>,  cudaFuncAttributeMaxDynamicSharedMemorySize, smem64);
    cudaFuncSetAttribute(k_pull, cudaFuncAttributeMaxDynamicSharedMemorySize, smemPull);

    const int pgrid = 304;            // 2 CTAs/SM * 152 SMs — persistent
    const int ggrid = N_PAD / 128;    // 782

    // front-end: counts (+x2h), scan (re-zeros g_cnt), scatter + inv emit
    k_count_x<<<(N_NODES * (D / 2) + 255) / 256, 256>>>(edst, etyp, E, x);
    k_scan<<<1, 1024>>>();
    k_scatter_coef<<<(E + 255) / 256, 256>>>(esrc, edst, etyp, E);

    // layer 0 (pull in ncu capture slot 4)
    k_pull<<<pgrid, 256, smemPull>>>(hx, comp0, invf);
    k_make_w_all<<<(3 * 128 * KDIM + 255) / 256, 256>>>(bases0, root0, bases1, root1,
                                                        bases2, root2);
    k_gemm<128, 1><<<ggrid, 256, smem128>>>(w0, hx, bias0, h0, D, 1, 0);

    // layer 1
    k_pull<<<pgrid, 256, smemPull>>>(h0, comp1, invf);
    k_gemm<128, 1><<<ggrid, 256, smem128>>>(w1, h0, bias1, h1, D, 1, 0);

    // layer 2 (d_out = 40)
    k_pull<<<pgrid, 256, smemPull>>>(h1, comp2, invf);
    k_gemm<64, 0><<<ggrid, 256, smem64>>>(w2, h1, bias2, out, 40, 0, 1);
}